// round 15
// baseline (speedup 1.0000x reference)
#include <cuda_runtime.h>
#include <cuda_bf16.h>
#include <math.h>

// Problem dims
#define T_STEPS 512
#define BATCH   64
#define ISZ     1024
#define HSZ     1024
#define GATES   4096   // 4*HSZ

// -------- scratch (__device__ globals; referenced ONLY from device code) ----
__device__ float g_xp[(size_t)T_STEPS * BATCH * GATES];  // 512 MB: x @ W_ih^T + bias
__device__ unsigned g_count;                             // grid barrier counter
// h state as pre-split bf16 hi/lo, DOUBLE-BUFFERED by step parity.
__device__ __align__(16) __nv_bfloat16 g_hhi[2][BATCH * HSZ];
__device__ __align__(16) __nv_bfloat16 g_hlo[2][BATCH * HSZ];
// pre-split GEMM operands (split ONCE; written by device kernels below)
__device__ __align__(16) __nv_bfloat16 g_xhi[(size_t)T_STEPS * BATCH * ISZ];
__device__ __align__(16) __nv_bfloat16 g_xlo[(size_t)T_STEPS * BATCH * ISZ];
__device__ __align__(16) __nv_bfloat16 g_whi[(size_t)GATES * ISZ];
__device__ __align__(16) __nv_bfloat16 g_wlo[(size_t)GATES * ISZ];

__global__ void reset_kernel() { g_count = 0u; }

// =====================================================================
// Common helpers
// =====================================================================
__device__ __forceinline__ void mma16816(float* c, const unsigned* a, const unsigned* b) {
    asm volatile("mma.sync.aligned.m16n8k16.row.col.f32.bf16.bf16.f32 "
                 "{%0,%1,%2,%3}, {%4,%5,%6,%7}, {%8,%9}, {%0,%1,%2,%3};\n"
                 : "+f"(c[0]), "+f"(c[1]), "+f"(c[2]), "+f"(c[3])
                 : "r"(a[0]), "r"(a[1]), "r"(a[2]), "r"(a[3]), "r"(b[0]), "r"(b[1]));
}

// Split a float4 into packed (hi, lo) bf16 pairs: lo = RN(v - hi)
__device__ __forceinline__ void split4(float4 v, uint2& hi, uint2& lo) {
    __nv_bfloat16 h0 = __float2bfloat16(v.x);
    __nv_bfloat16 h1 = __float2bfloat16(v.y);
    __nv_bfloat16 h2 = __float2bfloat16(v.z);
    __nv_bfloat16 h3 = __float2bfloat16(v.w);
    __nv_bfloat16 l0 = __float2bfloat16(v.x - __bfloat162float(h0));
    __nv_bfloat16 l1 = __float2bfloat16(v.y - __bfloat162float(h1));
    __nv_bfloat16 l2 = __float2bfloat16(v.z - __bfloat162float(h2));
    __nv_bfloat16 l3 = __float2bfloat16(v.w - __bfloat162float(h3));
    __nv_bfloat162 hp0 = __halves2bfloat162(h0, h1);
    __nv_bfloat162 hp1 = __halves2bfloat162(h2, h3);
    __nv_bfloat162 lp0 = __halves2bfloat162(l0, l1);
    __nv_bfloat162 lp1 = __halves2bfloat162(l2, l3);
    hi.x = *(unsigned*)&hp0; hi.y = *(unsigned*)&hp1;
    lo.x = *(unsigned*)&lp0; lo.y = *(unsigned*)&lp1;
}

__device__ __forceinline__ float sigf(float v) { return 1.f / (1.f + __expf(-v)); }

// h0 -> bf16 hi/lo split into buffer (T-1)&1 = 1 (read by step t = T-1)
__global__ __launch_bounds__(256) void h0split_kernel(const float* __restrict__ h0) {
    int i = blockIdx.x * blockDim.x + threadIdx.x;   // float4 index
    if (i >= BATCH * HSZ / 4) return;
    float4 v = ((const float4*)h0)[i];
    uint2 h, l;
    split4(v, h, l);
    *(uint2*)&g_hhi[1][i * 4] = h;
    *(uint2*)&g_hlo[1][i * 4] = l;
}

// One-time split of x into g_xhi/g_xlo (globals written from device code)
__global__ __launch_bounds__(256) void split_x_kernel(const float* __restrict__ src) {
    int i = blockIdx.x * blockDim.x + threadIdx.x;   // float4 index
    if (i >= T_STEPS * BATCH * ISZ / 4) return;
    float4 v = ((const float4*)src)[i];
    uint2 h, l;
    split4(v, h, l);
    *(uint2*)&g_xhi[(size_t)i * 4] = h;
    *(uint2*)&g_xlo[(size_t)i * 4] = l;
}

// One-time split of W_ih into g_whi/g_wlo
__global__ __launch_bounds__(256) void split_w_kernel(const float* __restrict__ src) {
    int i = blockIdx.x * blockDim.x + threadIdx.x;   // float4 index
    if (i >= GATES * ISZ / 4) return;
    float4 v = ((const float4*)src)[i];
    uint2 h, l;
    split4(v, h, l);
    *(uint2*)&g_whi[(size_t)i * 4] = h;
    *(uint2*)&g_wlo[(size_t)i * 4] = l;
}

// =====================================================================
// Kernel 1 (tensor cores): g_xp = x @ Wih^T + (bih + bhh)
//   bf16 split-3 (hh + hl + lh), fp32 accum; operands PRE-SPLIT in global.
// CTA 64x128, 8 warps (each 32x32), BK=32, 2 CTAs/SM.
// Register-prefetch double buffering of the (now bf16) global loads.
// =====================================================================
#define BMX 64
#define BNX 128
#define BKX 32
#define LDT 40   // smem row stride in bf16 (32 data + 8 pad); 80B = 5*16B aligned

__global__ __launch_bounds__(256, 2) void xp_mma_kernel(
    const float* __restrict__ bih, const float* __restrict__ bhh)
{
    __shared__ __nv_bfloat16 s_ah[BMX][LDT];
    __shared__ __nv_bfloat16 s_al[BMX][LDT];
    __shared__ __nv_bfloat16 s_bh[BNX][LDT];
    __shared__ __nv_bfloat16 s_bl[BNX][LDT];

    const int m0 = blockIdx.y * BMX;
    const int n0 = blockIdx.x * BNX;
    const int tid = threadIdx.x;
    const int lane = tid & 31;
    const int wid = tid >> 5;
    const int wm = wid & 1;    // 2 x 32 rows
    const int wn = wid >> 1;   // 4 x 32 cols
    const int gr = lane >> 2;  // 0..7
    const int gc = lane & 3;   // 0..3

    float acc[2][4][4];
    #pragma unroll
    for (int i = 0; i < 2; i++)
        #pragma unroll
        for (int j = 0; j < 4; j++)
            #pragma unroll
            for (int r = 0; r < 4; r++) acc[i][j][r] = 0.f;

    // prefetch registers: A (hi,lo) 1 chunk each; B (hi,lo) 2 chunks each
    uint4 pah, pal, pbh[2], pbl[2];
    auto load_regs = [&](int kt) {
        const int k0 = kt * BKX;
        {   // A: 64 rows x 32 bf16 = 256 x 16B chunks, 1 per thread
            int row = tid >> 2;              // 0..63
            int kc  = (tid & 3) << 3;        // 0,8,16,24 (bf16)
            size_t ga = (size_t)(m0 + row) * ISZ + k0 + kc;
            pah = *(const uint4*)&g_xhi[ga];
            pal = *(const uint4*)&g_xlo[ga];
        }
        #pragma unroll
        for (int i = 0; i < 2; i++) {        // B: 128 rows = 512 chunks, 2/thread
            int c   = tid + i * 256;         // 0..511
            int row = c >> 2;                // 0..127
            int kc  = (c & 3) << 3;
            size_t gb = (size_t)(n0 + row) * ISZ + k0 + kc;
            pbh[i] = *(const uint4*)&g_whi[gb];
            pbl[i] = *(const uint4*)&g_wlo[gb];
        }
    };

    const int NT = ISZ / BKX;  // 32
    load_regs(0);

    for (int kt = 0; kt < NT; kt++) {
        // store prefetched chunks -> smem (16B aligned: kc*2 in {0,16,32,48}, row pitch 80B)
        {
            int row = tid >> 2;
            int kc  = (tid & 3) << 3;
            *(uint4*)&s_ah[row][kc] = pah;
            *(uint4*)&s_al[row][kc] = pal;
        }
        #pragma unroll
        for (int i = 0; i < 2; i++) {
            int c   = tid + i * 256;
            int row = c >> 2;
            int kc  = (c & 3) << 3;
            *(uint4*)&s_bh[row][kc] = pbh[i];
            *(uint4*)&s_bl[row][kc] = pbl[i];
        }
        __syncthreads();
        if (kt + 1 < NT) load_regs(kt + 1);   // LDGs in flight during compute

        #pragma unroll
        for (int ks = 0; ks < 2; ks++) {
            const int cb = ks * 16 + gc * 2;
            unsigned ah[2][4], al[2][4];
            #pragma unroll
            for (int i = 0; i < 2; i++) {
                int r = wm * 32 + i * 16 + gr;
                ah[i][0] = *(const unsigned*)&s_ah[r    ][cb    ];
                ah[i][1] = *(const unsigned*)&s_ah[r + 8][cb    ];
                ah[i][2] = *(const unsigned*)&s_ah[r    ][cb + 8];
                ah[i][3] = *(const unsigned*)&s_ah[r + 8][cb + 8];
                al[i][0] = *(const unsigned*)&s_al[r    ][cb    ];
                al[i][1] = *(const unsigned*)&s_al[r + 8][cb    ];
                al[i][2] = *(const unsigned*)&s_al[r    ][cb + 8];
                al[i][3] = *(const unsigned*)&s_al[r + 8][cb + 8];
            }
            #pragma unroll
            for (int j = 0; j < 4; j++) {
                int bn = wn * 32 + j * 8 + gr;
                unsigned bhf[2], blf[2];
                bhf[0] = *(const unsigned*)&s_bh[bn][cb    ];
                bhf[1] = *(const unsigned*)&s_bh[bn][cb + 8];
                blf[0] = *(const unsigned*)&s_bl[bn][cb    ];
                blf[1] = *(const unsigned*)&s_bl[bn][cb + 8];
                #pragma unroll
                for (int i = 0; i < 2; i++) {
                    mma16816(acc[i][j], ah[i], bhf);
                    mma16816(acc[i][j], ah[i], blf);
                    mma16816(acc[i][j], al[i], bhf);
                }
            }
        }
        __syncthreads();
    }

    // epilogue: + (bih+bhh), store fp32 to g_xp
    #pragma unroll
    for (int i = 0; i < 2; i++) {
        int r0 = m0 + wm * 32 + i * 16 + gr;
        #pragma unroll
        for (int j = 0; j < 4; j++) {
            int c0 = n0 + wn * 32 + j * 8 + gc * 2;
            float b0 = __ldg(bih + c0) + __ldg(bhh + c0);
            float b1 = __ldg(bih + c0 + 1) + __ldg(bhh + c0 + 1);
            float2 v0 = make_float2(acc[i][j][0] + b0, acc[i][j][1] + b1);
            float2 v1 = make_float2(acc[i][j][2] + b0, acc[i][j][3] + b1);
            *(float2*)&g_xp[(size_t)r0 * GATES + c0] = v0;
            *(float2*)&g_xp[(size_t)(r0 + 8) * GATES + c0] = v1;
        }
    }
}

// =====================================================================
// Kernel 2: persistent reverse recurrence on TENSOR CORES.
// Unchanged from R14 (validated): W slab split once into SMEM; h chunk
// register-prefetch; parity double-buffered split h state; grid barrier.
// =====================================================================
#define NCTA 128
#define JPC  8
#define LDW  1032     // W slab row stride (bf16): 1024 + 8
#define KCH  128      // h K-chunk
#define LDH  136      // h chunk row stride (bf16): 128 + 8
#define LDP  33       // partial stride (fp32)

#define OFF_WH 0
#define OFF_WL (OFF_WH + 32 * LDW * 2)
#define OFF_HH (OFF_WL + 32 * LDW * 2)
#define OFF_HL (OFF_HH + 64 * LDH * 2)
#define OFF_P  (OFF_HL + 64 * LDH * 2)
#define SMEM_REC_BYTES (OFF_P + 2 * 64 * LDP * 4)   // 183808

__global__ __launch_bounds__(256) void lstm_recur_kernel(
    const float* __restrict__ c0, const float* __restrict__ Whh,
    float* __restrict__ out, int write_tail)
{
    extern __shared__ char smraw[];
    __nv_bfloat16* s_wh = (__nv_bfloat16*)(smraw + OFF_WH);  // [32][LDW]
    __nv_bfloat16* s_wl = (__nv_bfloat16*)(smraw + OFF_WL);
    __nv_bfloat16* s_hh = (__nv_bfloat16*)(smraw + OFF_HH);  // [64][LDH]
    __nv_bfloat16* s_hl = (__nv_bfloat16*)(smraw + OFF_HL);
    float*         s_p  = (float*)(smraw + OFF_P);           // [2][64][LDP]

    const int tid  = threadIdx.x;
    const int lane = tid & 31;
    const int wid  = tid >> 5;
    const int wm   = wid & 1;          // M half (32 batch rows)
    const int wn   = (wid >> 1) & 1;   // N half (16 slab cols)
    const int wk   = wid >> 2;         // K half (512 k each)
    const int gr   = lane >> 2;
    const int gc   = lane & 3;
    const int j0   = blockIdx.x * JPC;

    // ---- Preload + split W slab (stationary all steps) ----
    for (int f4 = tid; f4 < 32 * HSZ / 4; f4 += 256) {
        int e   = f4 * 4;
        int gcr = e >> 10;           // slab row 0..31
        int k   = e & 1023;
        int row = ((gcr >> 3) << 10) + j0 + (gcr & 7);   // q*1024 + j0 + jj
        float4 v = *(const float4*)(Whh + (size_t)row * HSZ + k);
        uint2 h, l;
        split4(v, h, l);
        *(uint2*)&s_wh[gcr * LDW + k] = h;
        *(uint2*)&s_wl[gcr * LDW + k] = l;
    }

    // ---- per-thread cell state ----
    float c_reg[2];
    #pragma unroll
    for (int e = 0; e < 2; e++) {
        int u = tid + e * 256;
        int b = u >> 3, jj = u & 7;
        c_reg[e] = c0[b * HSZ + j0 + jj];
    }
    __syncthreads();

    unsigned target = 0;
    for (int t = T_STEPS - 1; t >= 0; --t) {
        const int pr = t & 1;
        const int pw = 1 - pr;
        const __nv_bfloat16* hhi_r = g_hhi[pr];
        const __nv_bfloat16* hlo_r = g_hlo[pr];

        float xpg[2][4];
        #pragma unroll
        for (int e = 0; e < 2; e++) {
            int u = tid + e * 256;
            int b = u >> 3, jj = u & 7;
            size_t base = ((size_t)t * BATCH + b) * GATES + j0 + jj;
            xpg[e][0] = g_xp[base];
            xpg[e][1] = g_xp[base +     HSZ];
            xpg[e][2] = g_xp[base + 2 * HSZ];
            xpg[e][3] = g_xp[base + 3 * HSZ];
        }

        float acc[2][2][4];
        #pragma unroll
        for (int i = 0; i < 2; i++)
            #pragma unroll
            for (int j = 0; j < 2; j++)
                #pragma unroll
                for (int r = 0; r < 4; r++) acc[i][j][r] = 0.f;

        uint4 ph[4], pl[4];
        auto ldchunk = [&](int kc8) {
            #pragma unroll
            for (int i = 0; i < 4; i++) {
                int idx = tid + i * 256;
                int row = idx >> 4;
                int c16 = (idx & 15) << 3;
                size_t gsrc = (size_t)row * HSZ + kc8 * KCH + c16;
                ph[i] = *(const uint4*)&hhi_r[gsrc];
                pl[i] = *(const uint4*)&hlo_r[gsrc];
            }
        };
        ldchunk(0);

        for (int kc8 = 0; kc8 < HSZ / KCH; kc8++) {
            __syncthreads();
            #pragma unroll
            for (int i = 0; i < 4; i++) {
                int idx = tid + i * 256;
                int row = idx >> 4;
                int c16 = (idx & 15) << 3;
                *(uint4*)&s_hh[row * LDH + c16] = ph[i];
                *(uint4*)&s_hl[row * LDH + c16] = pl[i];
            }
            __syncthreads();
            if (kc8 + 1 < HSZ / KCH) ldchunk(kc8 + 1);

            #pragma unroll
            for (int k16 = 0; k16 < 4; k16++) {
                const int cbA = wk * 64 + k16 * 16 + gc * 2;
                const int cbB = kc8 * KCH + wk * 64 + k16 * 16 + gc * 2;
                unsigned ah[2][4], al[2][4];
                #pragma unroll
                for (int i = 0; i < 2; i++) {
                    int r = wm * 32 + i * 16 + gr;
                    ah[i][0] = *(const unsigned*)&s_hh[(r    ) * LDH + cbA    ];
                    ah[i][1] = *(const unsigned*)&s_hh[(r + 8) * LDH + cbA    ];
                    ah[i][2] = *(const unsigned*)&s_hh[(r    ) * LDH + cbA + 8];
                    ah[i][3] = *(const unsigned*)&s_hh[(r + 8) * LDH + cbA + 8];
                    al[i][0] = *(const unsigned*)&s_hl[(r    ) * LDH + cbA    ];
                    al[i][1] = *(const unsigned*)&s_hl[(r + 8) * LDH + cbA    ];
                    al[i][2] = *(const unsigned*)&s_hl[(r    ) * LDH + cbA + 8];
                    al[i][3] = *(const unsigned*)&s_hl[(r + 8) * LDH + cbA + 8];
                }
                #pragma unroll
                for (int j = 0; j < 2; j++) {
                    int bn = wn * 16 + j * 8 + gr;
                    unsigned bhf[2], blf[2];
                    bhf[0] = *(const unsigned*)&s_wh[bn * LDW + cbB    ];
                    bhf[1] = *(const unsigned*)&s_wh[bn * LDW + cbB + 8];
                    blf[0] = *(const unsigned*)&s_wl[bn * LDW + cbB    ];
                    blf[1] = *(const unsigned*)&s_wl[bn * LDW + cbB + 8];
                    #pragma unroll
                    for (int i = 0; i < 2; i++) {
                        mma16816(acc[i][j], ah[i], bhf);
                        mma16816(acc[i][j], ah[i], blf);
                        mma16816(acc[i][j], al[i], bhf);
                    }
                }
            }
        }

        __syncthreads();
        #pragma unroll
        for (int i = 0; i < 2; i++) {
            int r0 = wm * 32 + i * 16 + gr;
            #pragma unroll
            for (int j = 0; j < 2; j++) {
                int cc = wn * 16 + j * 8 + gc * 2;
                float* p = s_p + (wk * 64 + r0) * LDP + cc;
                p[0] = acc[i][j][0];
                p[1] = acc[i][j][1];
                p[8 * LDP] = acc[i][j][2];
                p[8 * LDP + 1] = acc[i][j][3];
            }
        }
        __syncthreads();

        #pragma unroll
        for (int e = 0; e < 2; e++) {
            int u = tid + e * 256;
            int b = u >> 3, jj = u & 7;
            int j = j0 + jj;
            float ri = s_p[b * LDP +      jj] + s_p[(64 + b) * LDP +      jj];
            float rf = s_p[b * LDP +  8 + jj] + s_p[(64 + b) * LDP +  8 + jj];
            float rg = s_p[b * LDP + 16 + jj] + s_p[(64 + b) * LDP + 16 + jj];
            float ro = s_p[b * LDP + 24 + jj] + s_p[(64 + b) * LDP + 24 + jj];
            float gi = sigf (xpg[e][0] + ri);
            float gf = sigf (xpg[e][1] + rf);
            float gg = tanhf(xpg[e][2] + rg);
            float go = sigf (xpg[e][3] + ro);
            float cn = fmaf(gf, c_reg[e], gi * gg);
            c_reg[e] = cn;
            float hn = go * tanhf(cn);
            out[((size_t)t * BATCH + b) * HSZ + j] = hn;
            __nv_bfloat16 hh = __float2bfloat16(hn);
            g_hhi[pw][b * HSZ + j] = hh;
            g_hlo[pw][b * HSZ + j] = __float2bfloat16(hn - __bfloat162float(hh));
            if (write_tail && t == 0) {
                out[(size_t)T_STEPS * BATCH * HSZ + b * HSZ + j] = hn;
                out[(size_t)T_STEPS * BATCH * HSZ + BATCH * HSZ + b * HSZ + j] = cn;
            }
        }
        __syncthreads();

        target += NCTA;
        if (tid == 0) {
            __threadfence();
            atomicAdd(&g_count, 1u);
            while (atomicAdd(&g_count, 0u) < target) __nanosleep(32);
            __threadfence();
        }
        __syncthreads();
    }
}

// =====================================================================
// kernel_launch — only harness pointers cross the host/device boundary.
// =====================================================================
extern "C" void kernel_launch(void* const* d_in, const int* in_sizes, int n_in,
                              void* d_out, int out_size)
{
    const float* x   = (const float*)d_in[0];
    const float* h0  = (const float*)d_in[1];
    const float* c0  = (const float*)d_in[2];
    const float* Wih = (const float*)d_in[3];
    const float* Whh = (const float*)d_in[4];
    const float* bih = (const float*)d_in[5];
    const float* bhh = (const float*)d_in[6];
    float* out = (float*)d_out;

    cudaFuncSetAttribute(lstm_recur_kernel,
                         cudaFuncAttributeMaxDynamicSharedMemorySize,
                         SMEM_REC_BYTES);

    reset_kernel<<<1, 1>>>();
    h0split_kernel<<<(BATCH * HSZ / 4 + 255) / 256, 256>>>(h0);

    // one-time pre-splits (device kernels write globals internally)
    split_x_kernel<<<(T_STEPS * BATCH * ISZ / 4 + 255) / 256, 256>>>(x);
    split_w_kernel<<<(GATES * ISZ / 4 + 255) / 256, 256>>>(Wih);

    xp_mma_kernel<<<dim3(GATES / BNX, (T_STEPS * BATCH) / BMX), 256>>>(bih, bhh);

    int write_tail = (out_size >= T_STEPS * BATCH * HSZ + 2 * BATCH * HSZ) ? 1 : 0;
    lstm_recur_kernel<<<NCTA, 256, SMEM_REC_BYTES>>>(
        c0, Whh, out, write_tail);
}

// round 16
// speedup vs baseline: 1.1366x; 1.1366x over previous
#include <cuda_runtime.h>
#include <cuda_bf16.h>
#include <math.h>

// Problem dims
#define T_STEPS 512
#define BATCH   64
#define ISZ     1024
#define HSZ     1024
#define GATES   4096   // 4*HSZ

// -------- scratch (__device__ globals; referenced ONLY from device code) ----
__device__ float g_xp[(size_t)T_STEPS * BATCH * GATES];  // 512 MB: x @ W_ih^T + bias
__device__ unsigned g_count;                             // grid barrier counter
// h state as pre-split bf16 hi/lo, DOUBLE-BUFFERED by step parity.
__device__ __align__(16) __nv_bfloat16 g_hhi[2][BATCH * HSZ];
__device__ __align__(16) __nv_bfloat16 g_hlo[2][BATCH * HSZ];

__global__ void reset_kernel() { g_count = 0u; }

// =====================================================================
// Common helpers
// =====================================================================
__device__ __forceinline__ void mma16816(float* c, const unsigned* a, const unsigned* b) {
    asm volatile("mma.sync.aligned.m16n8k16.row.col.f32.bf16.bf16.f32 "
                 "{%0,%1,%2,%3}, {%4,%5,%6,%7}, {%8,%9}, {%0,%1,%2,%3};\n"
                 : "+f"(c[0]), "+f"(c[1]), "+f"(c[2]), "+f"(c[3])
                 : "r"(a[0]), "r"(a[1]), "r"(a[2]), "r"(a[3]), "r"(b[0]), "r"(b[1]));
}

__device__ __forceinline__ void ldsm_x4(unsigned& r0, unsigned& r1,
                                        unsigned& r2, unsigned& r3, const void* p) {
    unsigned addr = (unsigned)__cvta_generic_to_shared(p);
    asm volatile("ldmatrix.sync.aligned.m8n8.x4.shared.b16 {%0,%1,%2,%3}, [%4];\n"
                 : "=r"(r0), "=r"(r1), "=r"(r2), "=r"(r3) : "r"(addr));
}

// Split a float4 into packed (hi, lo) bf16 pairs: lo = RN(v - hi)
__device__ __forceinline__ void split4(float4 v, uint2& hi, uint2& lo) {
    __nv_bfloat16 h0 = __float2bfloat16(v.x);
    __nv_bfloat16 h1 = __float2bfloat16(v.y);
    __nv_bfloat16 h2 = __float2bfloat16(v.z);
    __nv_bfloat16 h3 = __float2bfloat16(v.w);
    __nv_bfloat16 l0 = __float2bfloat16(v.x - __bfloat162float(h0));
    __nv_bfloat16 l1 = __float2bfloat16(v.y - __bfloat162float(h1));
    __nv_bfloat16 l2 = __float2bfloat16(v.z - __bfloat162float(h2));
    __nv_bfloat16 l3 = __float2bfloat16(v.w - __bfloat162float(h3));
    __nv_bfloat162 hp0 = __halves2bfloat162(h0, h1);
    __nv_bfloat162 hp1 = __halves2bfloat162(h2, h3);
    __nv_bfloat162 lp0 = __halves2bfloat162(l0, l1);
    __nv_bfloat162 lp1 = __halves2bfloat162(l2, l3);
    hi.x = *(unsigned*)&hp0; hi.y = *(unsigned*)&hp1;
    lo.x = *(unsigned*)&lp0; lo.y = *(unsigned*)&lp1;
}

__device__ __forceinline__ float sigf(float v) { return 1.f / (1.f + __expf(-v)); }

// h0 -> bf16 hi/lo split into buffer (T-1)&1 = 1 (read by step t = T-1)
__global__ __launch_bounds__(256) void h0split_kernel(const float* __restrict__ h0) {
    int i = blockIdx.x * blockDim.x + threadIdx.x;   // float4 index
    if (i >= BATCH * HSZ / 4) return;
    float4 v = ((const float4*)h0)[i];
    uint2 h, l;
    split4(v, h, l);
    *(uint2*)&g_hhi[1][i * 4] = h;
    *(uint2*)&g_hlo[1][i * 4] = l;
}

// =====================================================================
// Kernel 1 (tensor cores): g_xp = x @ Wih^T + (bih + bhh)
//   bf16 split-3 (hh + hl + lh), fp32 accum; in-kernel fp32->hi/lo split
//   (R14 winner). CTA 64x128, 8 warps (each 32x32), BK=32, 2 CTAs/SM.
//   Register-prefetch double buffering; ldmatrix.x4 fragment loads.
// =====================================================================
#define BMX 64
#define BNX 128
#define BKX 32
#define LDT 40   // smem row stride in bf16 (32 data + 8 pad); conflict-free

__global__ __launch_bounds__(256, 2) void xp_mma_kernel(
    const float* __restrict__ x, const float* __restrict__ Wih,
    const float* __restrict__ bih, const float* __restrict__ bhh)
{
    __shared__ __nv_bfloat16 s_ah[BMX][LDT];
    __shared__ __nv_bfloat16 s_al[BMX][LDT];
    __shared__ __nv_bfloat16 s_bh[BNX][LDT];
    __shared__ __nv_bfloat16 s_bl[BNX][LDT];

    const int m0 = blockIdx.y * BMX;
    const int n0 = blockIdx.x * BNX;
    const int tid = threadIdx.x;
    const int lane = tid & 31;
    const int wid = tid >> 5;
    const int wm = wid & 1;    // 2 x 32 rows
    const int wn = wid >> 1;   // 4 x 32 cols
    const int gr = lane >> 2;  // 0..7
    const int gc = lane & 3;   // 0..3

    float acc[2][4][4];
    #pragma unroll
    for (int i = 0; i < 2; i++)
        #pragma unroll
        for (int j = 0; j < 4; j++)
            #pragma unroll
            for (int r = 0; r < 4; r++) acc[i][j][r] = 0.f;

    float4 pa[2], pb[4];
    auto load_regs = [&](int kt) {
        const int k0 = kt * BKX;
        #pragma unroll
        for (int i = 0; i < 2; i++) {            // A: 64 rows = 512 float4
            int c   = tid + i * 256;
            int row = c >> 3;
            int kc  = (c & 7) << 2;
            pa[i] = *(const float4*)(x + (size_t)(m0 + row) * ISZ + k0 + kc);
        }
        #pragma unroll
        for (int i = 0; i < 4; i++) {            // B: 128 rows = 1024 float4
            int c   = tid + i * 256;
            int row = c >> 3;
            int kc  = (c & 7) << 2;
            pb[i] = *(const float4*)(Wih + (size_t)(n0 + row) * ISZ + k0 + kc);
        }
    };

    const int NT = ISZ / BKX;  // 32
    load_regs(0);

    for (int kt = 0; kt < NT; kt++) {
        // split prefetched regs -> smem
        #pragma unroll
        for (int i = 0; i < 2; i++) {
            int c   = tid + i * 256;
            int row = c >> 3;
            int kc  = (c & 7) << 2;
            uint2 h, l;
            split4(pa[i], h, l);
            *(uint2*)&s_ah[row][kc] = h;
            *(uint2*)&s_al[row][kc] = l;
        }
        #pragma unroll
        for (int i = 0; i < 4; i++) {
            int c   = tid + i * 256;
            int row = c >> 3;
            int kc  = (c & 7) << 2;
            uint2 h, l;
            split4(pb[i], h, l);
            *(uint2*)&s_bh[row][kc] = h;
            *(uint2*)&s_bl[row][kc] = l;
        }
        __syncthreads();
        if (kt + 1 < NT) load_regs(kt + 1);   // LDGs in flight during compute

        #pragma unroll
        for (int ks = 0; ks < 2; ks++) {
            // A fragments via ldmatrix.x4: lanes 0-15 rows, 16-31 -> col+8
            unsigned ah[2][4], al[2][4], bh[4][2], bl[4][2];
            #pragma unroll
            for (int i = 0; i < 2; i++) {
                int r   = wm * 32 + i * 16 + (lane & 15);
                int col = ks * 16 + (lane >> 4) * 8;
                ldsm_x4(ah[i][0], ah[i][1], ah[i][2], ah[i][3], &s_ah[r][col]);
                ldsm_x4(al[i][0], al[i][1], al[i][2], al[i][3], &s_al[r][col]);
            }
            // B fragments: x4 = 2 n8 frags x 2 k-halves
            #pragma unroll
            for (int jp = 0; jp < 2; jp++) {
                int nrow = wn * 32 + jp * 16 + (lane >> 4) * 8 + (lane & 7);
                int col  = ks * 16 + ((lane >> 3) & 1) * 8;
                unsigned r0, r1, r2, r3;
                ldsm_x4(r0, r1, r2, r3, &s_bh[nrow][col]);
                bh[2 * jp][0] = r0; bh[2 * jp][1] = r1;
                bh[2 * jp + 1][0] = r2; bh[2 * jp + 1][1] = r3;
                ldsm_x4(r0, r1, r2, r3, &s_bl[nrow][col]);
                bl[2 * jp][0] = r0; bl[2 * jp][1] = r1;
                bl[2 * jp + 1][0] = r2; bl[2 * jp + 1][1] = r3;
            }
            #pragma unroll
            for (int j = 0; j < 4; j++)
                #pragma unroll
                for (int i = 0; i < 2; i++) {
                    mma16816(acc[i][j], ah[i], bh[j]);
                    mma16816(acc[i][j], ah[i], bl[j]);
                    mma16816(acc[i][j], al[i], bh[j]);
                }
        }
        __syncthreads();
    }

    // epilogue: + (bih+bhh), store fp32 to g_xp
    #pragma unroll
    for (int i = 0; i < 2; i++) {
        int r0 = m0 + wm * 32 + i * 16 + gr;
        #pragma unroll
        for (int j = 0; j < 4; j++) {
            int c0 = n0 + wn * 32 + j * 8 + gc * 2;
            float b0 = __ldg(bih + c0) + __ldg(bhh + c0);
            float b1 = __ldg(bih + c0 + 1) + __ldg(bhh + c0 + 1);
            float2 v0 = make_float2(acc[i][j][0] + b0, acc[i][j][1] + b1);
            float2 v1 = make_float2(acc[i][j][2] + b0, acc[i][j][3] + b1);
            *(float2*)&g_xp[(size_t)r0 * GATES + c0] = v0;
            *(float2*)&g_xp[(size_t)(r0 + 8) * GATES + c0] = v1;
        }
    }
}

// =====================================================================
// Kernel 2: persistent reverse recurrence on TENSOR CORES.
// R14 structure (validated), fragment loads upgraded to ldmatrix.x4.
// =====================================================================
#define NCTA 128
#define JPC  8
#define LDW  1032     // W slab row stride (bf16): 1024 + 8
#define KCH  128      // h K-chunk
#define LDH  136      // h chunk row stride (bf16): 128 + 8
#define LDP  33       // partial stride (fp32)

#define OFF_WH 0
#define OFF_WL (OFF_WH + 32 * LDW * 2)
#define OFF_HH (OFF_WL + 32 * LDW * 2)
#define OFF_HL (OFF_HH + 64 * LDH * 2)
#define OFF_P  (OFF_HL + 64 * LDH * 2)
#define SMEM_REC_BYTES (OFF_P + 2 * 64 * LDP * 4)   // 183808

__global__ __launch_bounds__(256) void lstm_recur_kernel(
    const float* __restrict__ c0, const float* __restrict__ Whh,
    float* __restrict__ out, int write_tail)
{
    extern __shared__ char smraw[];
    __nv_bfloat16* s_wh = (__nv_bfloat16*)(smraw + OFF_WH);  // [32][LDW]
    __nv_bfloat16* s_wl = (__nv_bfloat16*)(smraw + OFF_WL);
    __nv_bfloat16* s_hh = (__nv_bfloat16*)(smraw + OFF_HH);  // [64][LDH]
    __nv_bfloat16* s_hl = (__nv_bfloat16*)(smraw + OFF_HL);
    float*         s_p  = (float*)(smraw + OFF_P);           // [2][64][LDP]

    const int tid  = threadIdx.x;
    const int lane = tid & 31;
    const int wid  = tid >> 5;
    const int wm   = wid & 1;          // M half (32 batch rows)
    const int wn   = (wid >> 1) & 1;   // N half (16 slab cols)
    const int wk   = wid >> 2;         // K half (512 k each)
    const int gr   = lane >> 2;
    const int gc   = lane & 3;
    const int j0   = blockIdx.x * JPC;

    // ---- Preload + split W slab (stationary all steps) ----
    for (int f4 = tid; f4 < 32 * HSZ / 4; f4 += 256) {
        int e   = f4 * 4;
        int gcr = e >> 10;
        int k   = e & 1023;
        int row = ((gcr >> 3) << 10) + j0 + (gcr & 7);   // q*1024 + j0 + jj
        float4 v = *(const float4*)(Whh + (size_t)row * HSZ + k);
        uint2 h, l;
        split4(v, h, l);
        *(uint2*)&s_wh[gcr * LDW + k] = h;
        *(uint2*)&s_wl[gcr * LDW + k] = l;
    }

    // ---- per-thread cell state ----
    float c_reg[2];
    #pragma unroll
    for (int e = 0; e < 2; e++) {
        int u = tid + e * 256;
        int b = u >> 3, jj = u & 7;
        c_reg[e] = c0[b * HSZ + j0 + jj];
    }
    __syncthreads();

    unsigned target = 0;
    for (int t = T_STEPS - 1; t >= 0; --t) {
        const int pr = t & 1;
        const int pw = 1 - pr;
        const __nv_bfloat16* hhi_r = g_hhi[pr];
        const __nv_bfloat16* hlo_r = g_hlo[pr];

        float xpg[2][4];
        #pragma unroll
        for (int e = 0; e < 2; e++) {
            int u = tid + e * 256;
            int b = u >> 3, jj = u & 7;
            size_t base = ((size_t)t * BATCH + b) * GATES + j0 + jj;
            xpg[e][0] = g_xp[base];
            xpg[e][1] = g_xp[base +     HSZ];
            xpg[e][2] = g_xp[base + 2 * HSZ];
            xpg[e][3] = g_xp[base + 3 * HSZ];
        }

        float acc[2][2][4];
        #pragma unroll
        for (int i = 0; i < 2; i++)
            #pragma unroll
            for (int j = 0; j < 2; j++)
                #pragma unroll
                for (int r = 0; r < 4; r++) acc[i][j][r] = 0.f;

        uint4 ph[4], pl[4];
        auto ldchunk = [&](int kc8) {
            #pragma unroll
            for (int i = 0; i < 4; i++) {
                int idx = tid + i * 256;
                int row = idx >> 4;
                int c16 = (idx & 15) << 3;
                size_t gsrc = (size_t)row * HSZ + kc8 * KCH + c16;
                ph[i] = *(const uint4*)&hhi_r[gsrc];
                pl[i] = *(const uint4*)&hlo_r[gsrc];
            }
        };
        ldchunk(0);

        for (int kc8 = 0; kc8 < HSZ / KCH; kc8++) {
            __syncthreads();
            #pragma unroll
            for (int i = 0; i < 4; i++) {
                int idx = tid + i * 256;
                int row = idx >> 4;
                int c16 = (idx & 15) << 3;
                *(uint4*)&s_hh[row * LDH + c16] = ph[i];
                *(uint4*)&s_hl[row * LDH + c16] = pl[i];
            }
            __syncthreads();
            if (kc8 + 1 < HSZ / KCH) ldchunk(kc8 + 1);

            #pragma unroll
            for (int k16 = 0; k16 < 4; k16++) {
                // A (h) fragments via ldmatrix.x4
                unsigned ah[2][4], al[2][4], bh[2][2], bl[2][2];
                #pragma unroll
                for (int i = 0; i < 2; i++) {
                    int r   = wm * 32 + i * 16 + (lane & 15);
                    int col = wk * 64 + k16 * 16 + (lane >> 4) * 8;
                    ldsm_x4(ah[i][0], ah[i][1], ah[i][2], ah[i][3], &s_hh[r * LDH + col]);
                    ldsm_x4(al[i][0], al[i][1], al[i][2], al[i][3], &s_hl[r * LDH + col]);
                }
                // B (W) fragments: one x4 covers both j frags (16 n-rows)
                {
                    int nrow = wn * 16 + (lane >> 4) * 8 + (lane & 7);
                    int col  = kc8 * KCH + wk * 64 + k16 * 16 + ((lane >> 3) & 1) * 8;
                    unsigned r0, r1, r2, r3;
                    ldsm_x4(r0, r1, r2, r3, &s_wh[nrow * LDW + col]);
                    bh[0][0] = r0; bh[0][1] = r1; bh[1][0] = r2; bh[1][1] = r3;
                    ldsm_x4(r0, r1, r2, r3, &s_wl[nrow * LDW + col]);
                    bl[0][0] = r0; bl[0][1] = r1; bl[1][0] = r2; bl[1][1] = r3;
                }
                #pragma unroll
                for (int j = 0; j < 2; j++)
                    #pragma unroll
                    for (int i = 0; i < 2; i++) {
                        mma16816(acc[i][j], ah[i], bh[j]);
                        mma16816(acc[i][j], ah[i], bl[j]);
                        mma16816(acc[i][j], al[i], bh[j]);
                    }
            }
        }

        __syncthreads();
        #pragma unroll
        for (int i = 0; i < 2; i++) {
            int r0 = wm * 32 + i * 16 + gr;
            #pragma unroll
            for (int j = 0; j < 2; j++) {
                int cc = wn * 16 + j * 8 + gc * 2;
                float* p = s_p + (wk * 64 + r0) * LDP + cc;
                p[0] = acc[i][j][0];
                p[1] = acc[i][j][1];
                p[8 * LDP] = acc[i][j][2];
                p[8 * LDP + 1] = acc[i][j][3];
            }
        }
        __syncthreads();

        #pragma unroll
        for (int e = 0; e < 2; e++) {
            int u = tid + e * 256;
            int b = u >> 3, jj = u & 7;
            int j = j0 + jj;
            float ri = s_p[b * LDP +      jj] + s_p[(64 + b) * LDP +      jj];
            float rf = s_p[b * LDP +  8 + jj] + s_p[(64 + b) * LDP +  8 + jj];
            float rg = s_p[b * LDP + 16 + jj] + s_p[(64 + b) * LDP + 16 + jj];
            float ro = s_p[b * LDP + 24 + jj] + s_p[(64 + b) * LDP + 24 + jj];
            float gi = sigf (xpg[e][0] + ri);
            float gf = sigf (xpg[e][1] + rf);
            float gg = tanhf(xpg[e][2] + rg);
            float go = sigf (xpg[e][3] + ro);
            float cn = fmaf(gf, c_reg[e], gi * gg);
            c_reg[e] = cn;
            float hn = go * tanhf(cn);
            out[((size_t)t * BATCH + b) * HSZ + j] = hn;
            __nv_bfloat16 hh = __float2bfloat16(hn);
            g_hhi[pw][b * HSZ + j] = hh;
            g_hlo[pw][b * HSZ + j] = __float2bfloat16(hn - __bfloat162float(hh));
            if (write_tail && t == 0) {
                out[(size_t)T_STEPS * BATCH * HSZ + b * HSZ + j] = hn;
                out[(size_t)T_STEPS * BATCH * HSZ + BATCH * HSZ + b * HSZ + j] = cn;
            }
        }
        __syncthreads();

        target += NCTA;
        if (tid == 0) {
            __threadfence();
            atomicAdd(&g_count, 1u);
            while (atomicAdd(&g_count, 0u) < target) __nanosleep(32);
            __threadfence();
        }
        __syncthreads();
    }
}

// =====================================================================
// kernel_launch — only harness pointers cross the host/device boundary.
// =====================================================================
extern "C" void kernel_launch(void* const* d_in, const int* in_sizes, int n_in,
                              void* d_out, int out_size)
{
    const float* x   = (const float*)d_in[0];
    const float* h0  = (const float*)d_in[1];
    const float* c0  = (const float*)d_in[2];
    const float* Wih = (const float*)d_in[3];
    const float* Whh = (const float*)d_in[4];
    const float* bih = (const float*)d_in[5];
    const float* bhh = (const float*)d_in[6];
    float* out = (float*)d_out;

    cudaFuncSetAttribute(lstm_recur_kernel,
                         cudaFuncAttributeMaxDynamicSharedMemorySize,
                         SMEM_REC_BYTES);

    reset_kernel<<<1, 1>>>();
    h0split_kernel<<<(BATCH * HSZ / 4 + 255) / 256, 256>>>(h0);

    xp_mma_kernel<<<dim3(GATES / BNX, (T_STEPS * BATCH) / BMX), 256>>>(
        x, Wih, bih, bhh);

    int write_tail = (out_size >= T_STEPS * BATCH * HSZ + 2 * BATCH * HSZ) ? 1 : 0;
    lstm_recur_kernel<<<NCTA, 256, SMEM_REC_BYTES>>>(
        c0, Whh, out, write_tail);
}